// round 7
// baseline (speedup 1.0000x reference)
#include <cuda_runtime.h>

// Elementwise affine: y = x * 2 + 5 over 8192*8192 fp32.
// ILP=4 x 128-bit per thread (measured Pareto optimum), with write-through
// stores (__stwt): writes go to DRAM in issue order instead of via deferred
// L2 dirty-eviction, testing whether writeback phasing is the residual
// DRAM-controller inefficiency. Loads stay evict-first streaming (__ldcs).
// 16777216 float4 total; 256 thr/block * 4 float4/thr -> 16384 blocks.

__global__ void __launch_bounds__(256) affine_kernel(const float4* __restrict__ x,
                                                     float4* __restrict__ y) {
    unsigned int base = blockIdx.x * 1024u + threadIdx.x;

    float4 v0 = __ldcs(&x[base]);
    float4 v1 = __ldcs(&x[base + 256u]);
    float4 v2 = __ldcs(&x[base + 512u]);
    float4 v3 = __ldcs(&x[base + 768u]);

    float4 r0, r1, r2, r3;
    r0.x = fmaf(v0.x, 2.0f, 5.0f); r0.y = fmaf(v0.y, 2.0f, 5.0f);
    r0.z = fmaf(v0.z, 2.0f, 5.0f); r0.w = fmaf(v0.w, 2.0f, 5.0f);
    r1.x = fmaf(v1.x, 2.0f, 5.0f); r1.y = fmaf(v1.y, 2.0f, 5.0f);
    r1.z = fmaf(v1.z, 2.0f, 5.0f); r1.w = fmaf(v1.w, 2.0f, 5.0f);
    r2.x = fmaf(v2.x, 2.0f, 5.0f); r2.y = fmaf(v2.y, 2.0f, 5.0f);
    r2.z = fmaf(v2.z, 2.0f, 5.0f); r2.w = fmaf(v2.w, 2.0f, 5.0f);
    r3.x = fmaf(v3.x, 2.0f, 5.0f); r3.y = fmaf(v3.y, 2.0f, 5.0f);
    r3.z = fmaf(v3.z, 2.0f, 5.0f); r3.w = fmaf(v3.w, 2.0f, 5.0f);

    __stwt(&y[base],         r0);
    __stwt(&y[base + 256u],  r1);
    __stwt(&y[base + 512u],  r2);
    __stwt(&y[base + 768u],  r3);
}

extern "C" void kernel_launch(void* const* d_in, const int* in_sizes, int n_in,
                              void* d_out, int out_size) {
    const float4* x = (const float4*)d_in[0];
    float4* y = (float4*)d_out;
    int n = in_sizes[0];            // 67108864
    int n4 = n / 4;                 // 16777216
    int blocks = n4 / 1024;         // 16384
    affine_kernel<<<blocks, 256>>>(x, y);
}

// round 8
// speedup vs baseline: 1.0082x; 1.0082x over previous
#include <cuda_runtime.h>

// Elementwise affine: y = x * 2 + 5 over 8192*8192 fp32. FINAL.
//
// Measured Pareto optimum across the full sweep (ILP 1/2/4/8, 128b vs 256b
// vector ops, .cs vs .wt stores): ILP=4 x 128-bit evict-first streaming
// loads/stores, 256 thr/block, 26 regs, occ ~77%.
//
// Bound: DRAM controller on the mixed 50/50 read+write stream at
// ~6.4-6.5 TB/s (81% of 8 TB/s spec). Not LTS-capped (~11 TB/s @NAT),
// not issue-capped (issue ~5%), not occupancy-capped. 512 MB traffic is
// irreducible. All alternatives measured within or below the ~1us
// run-to-run noise band.
// 16777216 float4 total; 256 thr/block * 4 float4/thr -> 16384 blocks.

__global__ void __launch_bounds__(256) affine_kernel(const float4* __restrict__ x,
                                                     float4* __restrict__ y) {
    unsigned int base = blockIdx.x * 1024u + threadIdx.x;

    float4 v0 = __ldcs(&x[base]);
    float4 v1 = __ldcs(&x[base + 256u]);
    float4 v2 = __ldcs(&x[base + 512u]);
    float4 v3 = __ldcs(&x[base + 768u]);

    float4 r0, r1, r2, r3;
    r0.x = fmaf(v0.x, 2.0f, 5.0f); r0.y = fmaf(v0.y, 2.0f, 5.0f);
    r0.z = fmaf(v0.z, 2.0f, 5.0f); r0.w = fmaf(v0.w, 2.0f, 5.0f);
    r1.x = fmaf(v1.x, 2.0f, 5.0f); r1.y = fmaf(v1.y, 2.0f, 5.0f);
    r1.z = fmaf(v1.z, 2.0f, 5.0f); r1.w = fmaf(v1.w, 2.0f, 5.0f);
    r2.x = fmaf(v2.x, 2.0f, 5.0f); r2.y = fmaf(v2.y, 2.0f, 5.0f);
    r2.z = fmaf(v2.z, 2.0f, 5.0f); r2.w = fmaf(v2.w, 2.0f, 5.0f);
    r3.x = fmaf(v3.x, 2.0f, 5.0f); r3.y = fmaf(v3.y, 2.0f, 5.0f);
    r3.z = fmaf(v3.z, 2.0f, 5.0f); r3.w = fmaf(v3.w, 2.0f, 5.0f);

    __stcs(&y[base],         r0);
    __stcs(&y[base + 256u],  r1);
    __stcs(&y[base + 512u],  r2);
    __stcs(&y[base + 768u],  r3);
}

extern "C" void kernel_launch(void* const* d_in, const int* in_sizes, int n_in,
                              void* d_out, int out_size) {
    const float4* x = (const float4*)d_in[0];
    float4* y = (float4*)d_out;
    int n = in_sizes[0];            // 67108864
    int n4 = n / 4;                 // 16777216
    int blocks = n4 / 1024;         // 16384
    affine_kernel<<<blocks, 256>>>(x, y);
}

// round 9
// speedup vs baseline: 1.0110x; 1.0027x over previous
#include <cuda_runtime.h>

// Elementwise affine: y = x * 2 + 5 over 8192*8192 fp32.
// Same per-thread geometry as the measured optimum (ILP=4 x 128-bit
// evict-first streaming, 64B/thread), but 512-thread CTAs: last untested
// axis (CTA granularity / wave-transition overhead / per-SM CTA count).
// 16777216 float4 total; 512 thr/block * 4 float4/thr -> 8192 blocks.

__global__ void __launch_bounds__(512) affine_kernel(const float4* __restrict__ x,
                                                     float4* __restrict__ y) {
    unsigned int base = blockIdx.x * 2048u + threadIdx.x;

    float4 v0 = __ldcs(&x[base]);
    float4 v1 = __ldcs(&x[base + 512u]);
    float4 v2 = __ldcs(&x[base + 1024u]);
    float4 v3 = __ldcs(&x[base + 1536u]);

    float4 r0, r1, r2, r3;
    r0.x = fmaf(v0.x, 2.0f, 5.0f); r0.y = fmaf(v0.y, 2.0f, 5.0f);
    r0.z = fmaf(v0.z, 2.0f, 5.0f); r0.w = fmaf(v0.w, 2.0f, 5.0f);
    r1.x = fmaf(v1.x, 2.0f, 5.0f); r1.y = fmaf(v1.y, 2.0f, 5.0f);
    r1.z = fmaf(v1.z, 2.0f, 5.0f); r1.w = fmaf(v1.w, 2.0f, 5.0f);
    r2.x = fmaf(v2.x, 2.0f, 5.0f); r2.y = fmaf(v2.y, 2.0f, 5.0f);
    r2.z = fmaf(v2.z, 2.0f, 5.0f); r2.w = fmaf(v2.w, 2.0f, 5.0f);
    r3.x = fmaf(v3.x, 2.0f, 5.0f); r3.y = fmaf(v3.y, 2.0f, 5.0f);
    r3.z = fmaf(v3.z, 2.0f, 5.0f); r3.w = fmaf(v3.w, 2.0f, 5.0f);

    __stcs(&y[base],          r0);
    __stcs(&y[base + 512u],   r1);
    __stcs(&y[base + 1024u],  r2);
    __stcs(&y[base + 1536u],  r3);
}

extern "C" void kernel_launch(void* const* d_in, const int* in_sizes, int n_in,
                              void* d_out, int out_size) {
    const float4* x = (const float4*)d_in[0];
    float4* y = (float4*)d_out;
    int n = in_sizes[0];            // 67108864
    int n4 = n / 4;                 // 16777216
    int blocks = n4 / 2048;         // 8192
    affine_kernel<<<blocks, 512>>>(x, y);
}